// round 10
// baseline (speedup 1.0000x reference)
#include <cuda_runtime.h>
#include <cuda_bf16.h>
#include <math.h>
#include <stdint.h>

// ---------------- problem constants ----------------
#define EMBED_DIM 256
#define N_LEVELS  4
#define N_POINTS  4
#define N_HEADS   8
#define HEAD_DIM  32
#define HMAXC     128
#define WMAXC     128
#define MAX_Q     8192
#define NCH       8          // K=256 / 32
#define EPSV      1e-5f

// ---------------- scratch (allocation-free) ----------------
__device__ float    g_off [MAX_Q * EMBED_DIM];
__device__ float    g_aw  [MAX_Q * (N_LEVELS * N_POINTS * N_HEADS)];
__device__ uint32_t g_qA  [2 * NCH * MAX_Q * 16];   // packed query (hi/lo planes)
__device__ uint32_t g_midA[2 * NCH * MAX_Q * 16];   // packed mid
__device__ uint32_t g_Woff [2 * NCH * 256 * 16];
__device__ uint32_t g_Watt [2 * NCH * 128 * 16];
__device__ uint32_t g_Wout [2 * NCH * 256 * 16];

// ---------------- bf16 helpers ----------------
__device__ __forceinline__ uint32_t pack_bf16x2(float lo, float hi) {
    uint32_t r;
    asm("cvt.rn.bf16x2.f32 %0, %1, %2;" : "=r"(r) : "f"(hi), "f"(lo));
    return r;
}
__device__ __forceinline__ float bf16lo_f(uint32_t w) { return __uint_as_float(w << 16); }
__device__ __forceinline__ float bf16hi_f(uint32_t w) { return __uint_as_float(w & 0xffff0000u); }

__device__ __forceinline__ void bf16split2(float x, float y, uint32_t& h, uint32_t& l) {
    h = pack_bf16x2(x, y);
    l = pack_bf16x2(x - bf16lo_f(h), y - bf16hi_f(h));
}

__device__ __forceinline__ void mma_bf16(float* d,
    uint32_t a0, uint32_t a1, uint32_t a2, uint32_t a3,
    uint32_t b0, uint32_t b1) {
    asm volatile(
        "mma.sync.aligned.m16n8k16.row.col.f32.bf16.bf16.f32 "
        "{%0,%1,%2,%3}, {%4,%5,%6,%7}, {%8,%9}, {%0,%1,%2,%3};\n"
        : "+f"(d[0]), "+f"(d[1]), "+f"(d[2]), "+f"(d[3])
        : "r"(a0), "r"(a1), "r"(a2), "r"(a3), "r"(b0), "r"(b1));
}

// permuted word index: k-pair kw (0..15) -> step*8 + (kw&3)*2 + ((kw>>2)&1)
__device__ __forceinline__ int widx(int kw) {
    return (kw >> 3) * 8 + (kw & 3) * 2 + ((kw >> 2) & 1);
}

// ---------------- cp.async ----------------
#define CP_ASYNC16(dst, src) \
    asm volatile("cp.async.ca.shared.global [%0], [%1], 16;\n" :: "r"(dst), "l"(src))
#define CP_COMMIT() asm volatile("cp.async.commit_group;\n" ::: "memory")
#define CP_WAIT(n)  asm volatile("cp.async.wait_group %0;\n" :: "n"(n) : "memory")

// ================= single merged prepack kernel =================
__global__ __launch_bounds__(128) void prepack_all_kernel(
    const float* __restrict__ query,
    const float* __restrict__ W_off, const float* __restrict__ W_attn,
    const float* __restrict__ W_out,
    uint32_t* __restrict__ pq, uint32_t* __restrict__ pwoff,
    uint32_t* __restrict__ pwatt, uint32_t* __restrict__ pwout,
    int Q)
{
    const int ch  = blockIdx.x;
    const int seg = blockIdx.y;
    const int nQseg = Q >> 7;
    const int tid = threadIdx.x;

    uint32_t hw[16], lw[16];

    if (seg < nQseg) {
        const int row = seg * 128 + tid;
        const float* src = query + (size_t)row * (NCH * 32) + ch * 32;
        #pragma unroll
        for (int kw = 0; kw < 16; kw++) {
            float2 v = *(const float2*)(src + 2 * kw);
            int w = widx(kw);
            bf16split2(v.x, v.y, hw[w], lw[w]);
        }
        size_t base = ((size_t)ch * Q + row) * 16;
        size_t pstr = (size_t)NCH * Q * 16;
        #pragma unroll
        for (int g = 0; g < 4; g++) {
            *(uint4*)&pq[base + g * 4]        = *(uint4*)&hw[g * 4];
            *(uint4*)&pq[pstr + base + g * 4] = *(uint4*)&lw[g * 4];
        }
    } else {
        const int wseg = seg - nQseg;
        const float* B; uint32_t* out; int N; int colOff;
        if (wseg == 0)      { B = W_off;  out = pwoff; N = 256; colOff = 0;   }
        else if (wseg == 1) { B = W_off;  out = pwoff; N = 256; colOff = 128; }
        else if (wseg == 2) { B = W_attn; out = pwatt; N = 128; colOff = 0;   }
        else if (wseg == 3) { B = W_out;  out = pwout; N = 256; colOff = 0;   }
        else                { B = W_out;  out = pwout; N = 256; colOff = 128; }
        const int n = colOff + tid;
        #pragma unroll
        for (int kw = 0; kw < 16; kw++) {
            int k = ch * 32 + 2 * kw;
            float x = B[(size_t)k * N + n];
            float y = B[(size_t)(k + 1) * N + n];
            int w = widx(kw);
            bf16split2(x, y, hw[w], lw[w]);
        }
        size_t base = ((size_t)ch * N + n) * 16;
        size_t pstr = (size_t)NCH * N * 16;
        #pragma unroll
        for (int g = 0; g < 4; g++) {
            *(uint4*)&out[base + g * 4]        = *(uint4*)&hw[g * 4];
            *(uint4*)&out[pstr + base + g * 4] = *(uint4*)&lw[g * 4];
        }
    }
}

// ================ bf16x3 mma GEMM on prepacked operands ================
// CTA tile 128x128, 256 threads, 8 warps (4m x 2n), warp tile 32x64.
#define SWA 24
#define SWB 24
#define A_W (128 * SWA)            // 3072 words per A plane
#define B_W (128 * SWB)            // 3072 words per B plane
#define BUF_W (2 * A_W + 2 * B_W)  // 12288 words per buffer
#define GEMM_SMEM (2 * BUF_W * 4)  // 98304 bytes

__global__ __launch_bounds__(256, 2) void gemm_packed_kernel(
    const uint32_t* __restrict__ Ap, int Qrows,
    const uint32_t* __restrict__ Bp0, const float* __restrict__ bias0,
    float* __restrict__ C0, int N0, int nb0,
    const uint32_t* __restrict__ Bp1, const float* __restrict__ bias1,
    float* __restrict__ C1, int N1)
{
    extern __shared__ uint32_t sm[];
    const int tid = threadIdx.x;
    const int lid = tid & 31;
    const int wid = tid >> 5;
    const int rowBase = blockIdx.y * 128;

    const uint32_t* Bp; const float* bias; float* C; int ldN; int colBase;
    if ((int)blockIdx.x < nb0) {
        Bp = Bp0; bias = bias0; C = C0; ldN = N0; colBase = blockIdx.x * 128;
    } else {
        Bp = Bp1; bias = bias1; C = C1; ldN = N1; colBase = (blockIdx.x - nb0) * 128;
    }

    const size_t Astr = (size_t)NCH * Qrows * 16;   // plane stride (words)
    const size_t Bstr = (size_t)NCH * ldN * 16;

    const int mOff = (wid >> 1) * 32;   // 4 m-warps
    const int nOff = (wid & 1) * 64;    // 2 n-warps, warp tile N=64
    const int gq = lid >> 2;
    const int tq = lid & 3;

    float acc[2][8][4];
    #pragma unroll
    for (int mt = 0; mt < 2; mt++)
        #pragma unroll
        for (int nt = 0; nt < 8; nt++)
            #pragma unroll
            for (int j = 0; j < 4; j++)
                acc[mt][nt][j] = 0.0f;

    // -------- async stage of one chunk into a buffer --------
    auto issue = [&](int ch, uint32_t* buf) {
        const uint32_t* asrc = Ap + ((size_t)ch * Qrows + rowBase) * 16;
        const uint32_t* bsrc = Bp + ((size_t)ch * ldN + colBase) * 16;
        #pragma unroll
        for (int i = 0; i < 4; i++) {                 // A: 1024 segs
            int s = tid + i * 256;
            int pl = s >> 9, rem = s & 511;
            int r = rem >> 2, g = rem & 3;
            uint32_t dst = (uint32_t)__cvta_generic_to_shared(
                buf + pl * A_W + r * SWA + g * 4);
            CP_ASYNC16(dst, asrc + pl * Astr + (size_t)r * 16 + g * 4);
        }
        #pragma unroll
        for (int i = 0; i < 4; i++) {                 // B: 1024 segs
            int s = tid + i * 256;
            int pl = s >> 9, rem = s & 511;
            int c = rem >> 2, g = rem & 3;
            uint32_t dst = (uint32_t)__cvta_generic_to_shared(
                buf + 2 * A_W + pl * B_W + c * SWB + g * 4);
            CP_ASYNC16(dst, bsrc + pl * Bstr + (size_t)c * 16 + g * 4);
        }
        CP_COMMIT();
    };

    issue(0, sm);

    for (int ch = 0; ch < NCH; ch++) {
        if (ch + 1 < NCH) {
            issue(ch + 1, sm + ((ch + 1) & 1) * BUF_W);
            CP_WAIT(1);
        } else {
            CP_WAIT(0);
        }
        __syncthreads();

        const uint32_t* bAh = sm + (ch & 1) * BUF_W;
        const uint32_t* bAl = bAh + A_W;
        const uint32_t* bBh = bAh + 2 * A_W;
        const uint32_t* bBl = bBh + B_W;

        #pragma unroll
        for (int step = 0; step < 2; step++) {
            const int s8 = step * 8;
            uint2 pah[2], qah[2], pal[2], qal[2];
            #pragma unroll
            for (int mt = 0; mt < 2; mt++) {
                int row = mOff + mt * 16 + gq;
                pah[mt] = *(const uint2*)&bAh[row * SWA + s8 + tq * 2];
                qah[mt] = *(const uint2*)&bAh[(row + 8) * SWA + s8 + tq * 2];
                pal[mt] = *(const uint2*)&bAl[row * SWA + s8 + tq * 2];
                qal[mt] = *(const uint2*)&bAl[(row + 8) * SWA + s8 + tq * 2];
            }
            // process B in two 32-col halves to cap live registers
            #pragma unroll
            for (int nh = 0; nh < 2; nh++) {
                uint2 bhf[4], blf[4];
                #pragma unroll
                for (int nt = 0; nt < 4; nt++) {
                    int col = nOff + nh * 32 + nt * 8 + gq;
                    bhf[nt] = *(const uint2*)&bBh[col * SWB + s8 + tq * 2];
                    blf[nt] = *(const uint2*)&bBl[col * SWB + s8 + tq * 2];
                }
                #pragma unroll
                for (int mt = 0; mt < 2; mt++)
                    #pragma unroll
                    for (int nt = 0; nt < 4; nt++)
                        mma_bf16(acc[mt][nh * 4 + nt],
                                 pah[mt].x, qah[mt].x, pah[mt].y, qah[mt].y,
                                 bhf[nt].x, bhf[nt].y);
                #pragma unroll
                for (int mt = 0; mt < 2; mt++)
                    #pragma unroll
                    for (int nt = 0; nt < 4; nt++)
                        mma_bf16(acc[mt][nh * 4 + nt],
                                 pal[mt].x, qal[mt].x, pal[mt].y, qal[mt].y,
                                 bhf[nt].x, bhf[nt].y);
                #pragma unroll
                for (int mt = 0; mt < 2; mt++)
                    #pragma unroll
                    for (int nt = 0; nt < 4; nt++)
                        mma_bf16(acc[mt][nh * 4 + nt],
                                 pah[mt].x, qah[mt].x, pah[mt].y, qah[mt].y,
                                 blf[nt].x, blf[nt].y);
            }
        }
        __syncthreads();
    }

    // ---- epilogue: direct float2 stores + bias ----
    #pragma unroll
    for (int mt = 0; mt < 2; mt++) {
        int row = rowBase + mOff + mt * 16 + gq;
        #pragma unroll
        for (int nt = 0; nt < 8; nt++) {
            int col = colBase + nOff + (nt >> 2) * 32 + (nt & 3) * 8 + 2 * tq;
            float2 bs = *(const float2*)(bias + col);
            float2 v0, v1;
            v0.x = acc[mt][nt][0] + bs.x;
            v0.y = acc[mt][nt][1] + bs.y;
            v1.x = acc[mt][nt][2] + bs.x;
            v1.y = acc[mt][nt][3] + bs.y;
            *(float2*)(C + (size_t)row * ldN + col) = v0;
            *(float2*)(C + (size_t)(row + 8) * ldN + col) = v1;
        }
    }
}

// ---------------- sampling kernel: softmax + bilinear gather ----------------
// 2 queries per block, 512 threads. Writes packed bf16 hi/lo mid for GEMM2.
__global__ __launch_bounds__(512) void msda_sample_kernel(
    const float* __restrict__ off,
    const float* __restrict__ awr,
    const float* __restrict__ xyref,
    const float* __restrict__ V,
    const int*   __restrict__ batch_offsets,
    const int*   __restrict__ spatial_shapes,
    uint32_t* __restrict__ midp,
    int Q)
{
    const int tid  = threadIdx.x;
    const int sub  = tid >> 8;
    const int stid = tid & 255;
    const int q    = blockIdx.x * 2 + sub;

    __shared__ float4 s_w[2][16][8];
    __shared__ int4   s_b[2][16][8];
    __shared__ float  s_e[2][16][8];
    __shared__ float  s_inv[2][8];

    if (stid < 128) {
        s_e[sub][stid >> 3][stid & 7] = awr[(long)q * 128 + stid];
    }
    __syncthreads();

    if (stid < 8) {
        float m = -1e30f;
        #pragma unroll
        for (int lp = 0; lp < 16; lp++) m = fmaxf(m, s_e[sub][lp][stid]);
        float s = 0.0f;
        #pragma unroll
        for (int lp = 0; lp < 16; lp++) {
            float e = __expf(s_e[sub][lp][stid] - m);
            s_e[sub][lp][stid] = e;
            s += e;
        }
        s_inv[sub][stid] = 1.0f / s;
    }
    __syncthreads();

    if (stid < 128) {
        const int lp = stid >> 3;
        const int h  = stid & 7;
        const int l  = lp >> 2;

        const int   wi  = spatial_shapes[l * 2 + 1];
        const int   hi  = spatial_shapes[l * 2 + 0];
        const float wsz = (float)wi;
        const float hsz = (float)hi;
        const int   wcap = wi - 1;
        const int   hcap = hi - 1;

        float rx = fminf(fmaxf(xyref[(long)q * 2 + 0], 0.0f), 1.0f);
        float ry = fminf(fmaxf(xyref[(long)q * 2 + 1], 0.0f), 1.0f);
        float invx = __logf(fminf(fmaxf(rx, EPSV), 1.0f) / fminf(fmaxf(1.0f - rx, EPSV), 1.0f));
        float invy = __logf(fminf(fmaxf(ry, EPSV), 1.0f) / fminf(fmaxf(1.0f - ry, EPSV), 1.0f));

        float ox = off[(long)q * 256 + lp * 16 + h * 2 + 0];
        float oy = off[(long)q * 256 + lp * 16 + h * 2 + 1];

        float sx = 1.0f / (1.0f + __expf(-(invx + ox)));
        float sy = 1.0f / (1.0f + __expf(-(invy + oy)));
        float locx = sx * 2.0f - 1.0f;
        float locy = sy * 2.0f - 1.0f;
        // NB: reference pairs loc[...,0] with w_sz and uses x as the FIRST
        // spatial index (H axis). Replicate exactly.
        float x = ((locx + 1.0f) * wsz - 1.0f) * 0.5f;
        float y = ((locy + 1.0f) * hsz - 1.0f) * 0.5f;

        int x0 = (int)floorf(x);
        int y0 = (int)floorf(y);
        int x1c = min(max(x0 + 1, 0), wcap);
        int x0c = min(max(x0,     0), wcap);
        int y1c = min(max(y0 + 1, 0), hcap);
        int y0c = min(max(y0,     0), hcap);

        float x0f = (float)x0c, x1f = (float)x1c;
        float y0f = (float)y0c, y1f = (float)y1c;
        float wa = (x1f - x) * (y1f - y);
        float wb = (x1f - x) * (y - y0f);
        float wc = (x - x0f) * (y1f - y);
        float wd = (x - x0f) * (y - y0f);

        float aw = s_e[sub][lp][h] * s_inv[sub][h];

        int b  = (q >= batch_offsets[1]) ? 1 : 0;
        int bb = b * HMAXC;
        int hd = h * HEAD_DIM;
        int base00 = (((bb + x0c) * WMAXC + y0c) * N_LEVELS + l) * EMBED_DIM + hd;
        int base01 = (((bb + x0c) * WMAXC + y1c) * N_LEVELS + l) * EMBED_DIM + hd;
        int base10 = (((bb + x1c) * WMAXC + y0c) * N_LEVELS + l) * EMBED_DIM + hd;
        int base11 = (((bb + x1c) * WMAXC + y1c) * N_LEVELS + l) * EMBED_DIM + hd;

        s_w[sub][lp][h] = make_float4(wa * aw, wb * aw, wc * aw, wd * aw);
        s_b[sub][lp][h] = make_int4(base00, base01, base10, base11);
    }
    __syncthreads();

    const int h = (stid >> 5) & 7;
    const int d = stid & 31;
    float acc = 0.0f;
    #pragma unroll 4
    for (int lp = 0; lp < 16; lp++) {
        float4 w  = s_w[sub][lp][h];
        int4   bs = s_b[sub][lp][h];
        float v0 = __ldg(V + bs.x + d);
        float v1 = __ldg(V + bs.y + d);
        float v2 = __ldg(V + bs.z + d);
        float v3 = __ldg(V + bs.w + d);
        acc = fmaf(w.x, v0, acc);
        acc = fmaf(w.y, v1, acc);
        acc = fmaf(w.z, v2, acc);
        acc = fmaf(w.w, v3, acc);
    }

    // pack (c, c+1) pairs into bf16 hi/lo planes of midA
    float nbr = __shfl_xor_sync(0xffffffffu, acc, 1);
    if ((d & 1) == 0) {
        uint32_t hw, lw;
        bf16split2(acc, nbr, hw, lw);
        int c  = h * 32 + d;
        int kp = c >> 1;
        int ch = kp >> 4;
        int w  = widx(kp & 15);
        size_t base = ((size_t)ch * Q + q) * 16 + w;
        size_t pstr = (size_t)NCH * Q * 16;
        midp[base]        = hw;
        midp[pstr + base] = lw;
    }
}

// ---------------- launch ----------------
extern "C" void kernel_launch(void* const* d_in, const int* in_sizes, int n_in,
                              void* d_out, int out_size)
{
    const float* query  = (const float*)d_in[0];
    const float* xyref  = (const float*)d_in[1];
    const float* V      = (const float*)d_in[2];
    const float* W_off  = (const float*)d_in[3];
    const float* b_off  = (const float*)d_in[4];
    const float* W_attn = (const float*)d_in[5];
    const float* b_attn = (const float*)d_in[6];
    const float* W_out  = (const float*)d_in[7];
    const float* b_out  = (const float*)d_in[8];
    const int* batch_offsets  = (const int*)d_in[9];
    const int* spatial_shapes = (const int*)d_in[10];
    float* out = (float*)d_out;

    const int Q = in_sizes[0] / EMBED_DIM;

    float *p_off, *p_aw;
    uint32_t *p_qA, *p_midA, *p_Woff, *p_Watt, *p_Wout;
    cudaGetSymbolAddress((void**)&p_off,  g_off);
    cudaGetSymbolAddress((void**)&p_aw,   g_aw);
    cudaGetSymbolAddress((void**)&p_qA,   g_qA);
    cudaGetSymbolAddress((void**)&p_midA, g_midA);
    cudaGetSymbolAddress((void**)&p_Woff, g_Woff);
    cudaGetSymbolAddress((void**)&p_Watt, g_Watt);
    cudaGetSymbolAddress((void**)&p_Wout, g_Wout);

    cudaFuncSetAttribute(gemm_packed_kernel,
                         cudaFuncAttributeMaxDynamicSharedMemorySize, GEMM_SMEM);

    // single merged prepack: query + all 3 weight matrices
    prepack_all_kernel<<<dim3(NCH, Q / 128 + 5), 128>>>(
        query, W_off, W_attn, W_out,
        p_qA, p_Woff, p_Watt, p_Wout, Q);

    // fused GEMM1: off (2 col-blocks of 128) + aw (1 col-block of 128)
    gemm_packed_kernel<<<dim3(3, Q / 128), 256, GEMM_SMEM>>>(
        p_qA, Q,
        p_Woff, b_off, p_off, EMBED_DIM, 2,
        p_Watt, b_attn, p_aw, 128);

    // softmax + deformable sampling -> packed mid (2 queries per block)
    msda_sample_kernel<<<Q / 2, 512>>>(
        p_off, p_aw, xyref, V, batch_offsets, spatial_shapes, p_midA, Q);

    // GEMM2: out = mid @ W_out + b_out (2 col-blocks of 128)
    gemm_packed_kernel<<<dim3(2, Q / 128), 256, GEMM_SMEM>>>(
        p_midA, Q,
        p_Wout, b_out, out, EMBED_DIM, 2,
        nullptr, nullptr, nullptr, 128);
}

// round 11
// speedup vs baseline: 1.1030x; 1.1030x over previous
#include <cuda_runtime.h>
#include <cuda_bf16.h>
#include <math.h>
#include <stdint.h>

// ---------------- problem constants ----------------
#define EMBED_DIM 256
#define N_LEVELS  4
#define N_POINTS  4
#define N_HEADS   8
#define HEAD_DIM  32
#define HMAXC     128
#define WMAXC     128
#define MAX_Q     8192
#define NCH       8          // K=256 / 32
#define EPSV      1e-5f

// ---------------- scratch (allocation-free) ----------------
__device__ float    g_off [MAX_Q * EMBED_DIM];
__device__ float    g_aw  [MAX_Q * (N_LEVELS * N_POINTS * N_HEADS)];
__device__ uint32_t g_qA  [2 * NCH * MAX_Q * 16];   // packed query (hi/lo planes)
__device__ uint32_t g_midA[2 * NCH * MAX_Q * 16];   // packed mid
__device__ uint32_t g_Woff [2 * NCH * 256 * 16];
__device__ uint32_t g_Watt [2 * NCH * 128 * 16];
__device__ uint32_t g_Wout [2 * NCH * 256 * 16];

// ---------------- bf16 helpers ----------------
__device__ __forceinline__ uint32_t pack_bf16x2(float lo, float hi) {
    uint32_t r;
    asm("cvt.rn.bf16x2.f32 %0, %1, %2;" : "=r"(r) : "f"(hi), "f"(lo));
    return r;
}
__device__ __forceinline__ float bf16lo_f(uint32_t w) { return __uint_as_float(w << 16); }
__device__ __forceinline__ float bf16hi_f(uint32_t w) { return __uint_as_float(w & 0xffff0000u); }

__device__ __forceinline__ void bf16split2(float x, float y, uint32_t& h, uint32_t& l) {
    h = pack_bf16x2(x, y);
    l = pack_bf16x2(x - bf16lo_f(h), y - bf16hi_f(h));
}

__device__ __forceinline__ void mma_bf16(float* d,
    uint32_t a0, uint32_t a1, uint32_t a2, uint32_t a3,
    uint32_t b0, uint32_t b1) {
    asm volatile(
        "mma.sync.aligned.m16n8k16.row.col.f32.bf16.bf16.f32 "
        "{%0,%1,%2,%3}, {%4,%5,%6,%7}, {%8,%9}, {%0,%1,%2,%3};\n"
        : "+f"(d[0]), "+f"(d[1]), "+f"(d[2]), "+f"(d[3])
        : "r"(a0), "r"(a1), "r"(a2), "r"(a3), "r"(b0), "r"(b1));
}

// step-innermost permutation: kpair kw (0..15) -> (kw&3)*4 + (kw>>3)*2 + ((kw>>2)&1)
// so thread tq's LDS.128 at word tq*4 gets {s0e0, s0e1, s1e0, s1e1}
__device__ __forceinline__ int widx2(int kw) {
    return (kw & 3) * 4 + (kw >> 3) * 2 + ((kw >> 2) & 1);
}

// ---------------- cp.async (L1-bypass) ----------------
#define CP_ASYNC16(dst, src) \
    asm volatile("cp.async.cg.shared.global [%0], [%1], 16;\n" :: "r"(dst), "l"(src))
#define CP_COMMIT() asm volatile("cp.async.commit_group;\n" ::: "memory")
#define CP_WAIT(n)  asm volatile("cp.async.wait_group %0;\n" :: "n"(n) : "memory")

// ================= single merged prepack kernel =================
__global__ __launch_bounds__(128) void prepack_all_kernel(
    const float* __restrict__ query,
    const float* __restrict__ W_off, const float* __restrict__ W_attn,
    const float* __restrict__ W_out,
    uint32_t* __restrict__ pq, uint32_t* __restrict__ pwoff,
    uint32_t* __restrict__ pwatt, uint32_t* __restrict__ pwout,
    int Q)
{
    const int ch  = blockIdx.x;
    const int seg = blockIdx.y;
    const int nQseg = Q >> 7;
    const int tid = threadIdx.x;

    uint32_t hw[16], lw[16];

    if (seg < nQseg) {
        const int row = seg * 128 + tid;
        const float* src = query + (size_t)row * (NCH * 32) + ch * 32;
        #pragma unroll
        for (int kw = 0; kw < 16; kw++) {
            float2 v = *(const float2*)(src + 2 * kw);
            int w = widx2(kw);
            bf16split2(v.x, v.y, hw[w], lw[w]);
        }
        size_t base = ((size_t)ch * Q + row) * 16;
        size_t pstr = (size_t)NCH * Q * 16;
        #pragma unroll
        for (int g = 0; g < 4; g++) {
            *(uint4*)&pq[base + g * 4]        = *(uint4*)&hw[g * 4];
            *(uint4*)&pq[pstr + base + g * 4] = *(uint4*)&lw[g * 4];
        }
    } else {
        const int wseg = seg - nQseg;
        const float* B; uint32_t* out; int N; int colOff;
        if (wseg == 0)      { B = W_off;  out = pwoff; N = 256; colOff = 0;   }
        else if (wseg == 1) { B = W_off;  out = pwoff; N = 256; colOff = 128; }
        else if (wseg == 2) { B = W_attn; out = pwatt; N = 128; colOff = 0;   }
        else if (wseg == 3) { B = W_out;  out = pwout; N = 256; colOff = 0;   }
        else                { B = W_out;  out = pwout; N = 256; colOff = 128; }
        const int n = colOff + tid;
        #pragma unroll
        for (int kw = 0; kw < 16; kw++) {
            int k = ch * 32 + 2 * kw;
            float x = B[(size_t)k * N + n];
            float y = B[(size_t)(k + 1) * N + n];
            int w = widx2(kw);
            bf16split2(x, y, hw[w], lw[w]);
        }
        size_t base = ((size_t)ch * N + n) * 16;
        size_t pstr = (size_t)NCH * N * 16;
        #pragma unroll
        for (int g = 0; g < 4; g++) {
            *(uint4*)&out[base + g * 4]        = *(uint4*)&hw[g * 4];
            *(uint4*)&out[pstr + base + g * 4] = *(uint4*)&lw[g * 4];
        }
    }
}

// ================ bf16x3 mma GEMM on prepacked operands ================
// CTA tile 128x64, 256 threads, 8 warps (4m x 2n), warp tile 32x32.
// Dense smem: 16 words/row (no pad) -> LDS.128 conflict-free, chunks contiguous.
#define A_W (128 * 16)             // 2048 words per A plane
#define B_W (64 * 16)              // 1024 words per B plane
#define BUF_W (2 * A_W + 2 * B_W)  // 6144 words per buffer
#define GEMM_SMEM (2 * BUF_W * 4)  // 49152 bytes

__global__ __launch_bounds__(256, 2) void gemm_packed_kernel(
    const uint32_t* __restrict__ Ap, int Qrows,
    const uint32_t* __restrict__ Bp0, const float* __restrict__ bias0,
    float* __restrict__ C0, int N0, int nb0,
    const uint32_t* __restrict__ Bp1, const float* __restrict__ bias1,
    float* __restrict__ C1, int N1)
{
    extern __shared__ uint32_t sm[];
    const int tid = threadIdx.x;
    const int lid = tid & 31;
    const int wid = tid >> 5;
    const int rowBase = blockIdx.y * 128;

    const uint32_t* Bp; const float* bias; float* C; int ldN; int colBase;
    if ((int)blockIdx.x < nb0) {
        Bp = Bp0; bias = bias0; C = C0; ldN = N0; colBase = blockIdx.x * 64;
    } else {
        Bp = Bp1; bias = bias1; C = C1; ldN = N1; colBase = (blockIdx.x - nb0) * 64;
    }

    const size_t Astr = (size_t)NCH * Qrows * 16;   // plane stride (words)
    const size_t Bstr = (size_t)NCH * ldN * 16;

    const int mOff = (wid >> 1) * 32;
    const int nOff = (wid & 1) * 32;
    const int gq = lid >> 2;
    const int tq = lid & 3;

    float acc[2][4][4];
    #pragma unroll
    for (int mt = 0; mt < 2; mt++)
        #pragma unroll
        for (int nt = 0; nt < 4; nt++)
            #pragma unroll
            for (int j = 0; j < 4; j++)
                acc[mt][nt][j] = 0.0f;

    // -------- async stage of one chunk (contiguous planes) --------
    auto issue = [&](int ch, uint32_t* buf) {
        const uint32_t* asrc = Ap + ((size_t)ch * Qrows + rowBase) * 16;
        const uint32_t* bsrc = Bp + ((size_t)ch * ldN + colBase) * 16;
        #pragma unroll
        for (int i = 0; i < 4; i++) {                 // A: 1024 segs (2 planes x 512)
            int s = tid + i * 256;
            int pl = s >> 9, rem = s & 511;
            uint32_t dst = (uint32_t)__cvta_generic_to_shared(
                buf + pl * A_W + rem * 4);
            CP_ASYNC16(dst, asrc + pl * Astr + (size_t)rem * 4);
        }
        #pragma unroll
        for (int i = 0; i < 2; i++) {                 // B: 512 segs (2 planes x 256)
            int s = tid + i * 256;
            int pl = s >> 8, rem = s & 255;
            uint32_t dst = (uint32_t)__cvta_generic_to_shared(
                buf + 2 * A_W + pl * B_W + rem * 4);
            CP_ASYNC16(dst, bsrc + pl * Bstr + (size_t)rem * 4);
        }
        CP_COMMIT();
    };

    issue(0, sm);

    for (int ch = 0; ch < NCH; ch++) {
        if (ch + 1 < NCH) {
            issue(ch + 1, sm + ((ch + 1) & 1) * BUF_W);
            CP_WAIT(1);
        } else {
            CP_WAIT(0);
        }
        __syncthreads();

        const uint32_t* bAh = sm + (ch & 1) * BUF_W;
        const uint32_t* bAl = bAh + A_W;
        const uint32_t* bBh = bAh + 2 * A_W;
        const uint32_t* bBl = bBh + B_W;

        // ---- load ALL fragments for both k16 steps: 16 LDS.128 ----
        // uint4 = {s0e0, s0e1, s1e0, s1e1}
        uint4 PAh[2], QAh[2], PAl[2], QAl[2];   // row / row+8
        uint4 BH[4], BL[4];
        #pragma unroll
        for (int mt = 0; mt < 2; mt++) {
            int row = mOff + mt * 16 + gq;
            PAh[mt] = *(const uint4*)&bAh[row * 16 + tq * 4];
            QAh[mt] = *(const uint4*)&bAh[(row + 8) * 16 + tq * 4];
            PAl[mt] = *(const uint4*)&bAl[row * 16 + tq * 4];
            QAl[mt] = *(const uint4*)&bAl[(row + 8) * 16 + tq * 4];
        }
        #pragma unroll
        for (int nt = 0; nt < 4; nt++) {
            int col = nOff + nt * 8 + gq;
            BH[nt] = *(const uint4*)&bBh[col * 16 + tq * 4];
            BL[nt] = *(const uint4*)&bBl[col * 16 + tq * 4];
        }

        // ---- step 0 (x/y lanes), then step 1 (z/w lanes): 48 HMMA ----
        #pragma unroll
        for (int mt = 0; mt < 2; mt++)
            #pragma unroll
            for (int nt = 0; nt < 4; nt++) {
                mma_bf16(acc[mt][nt], PAh[mt].x, QAh[mt].x, PAh[mt].y, QAh[mt].y,
                         BH[nt].x, BH[nt].y);
                mma_bf16(acc[mt][nt], PAl[mt].x, QAl[mt].x, PAl[mt].y, QAl[mt].y,
                         BH[nt].x, BH[nt].y);
                mma_bf16(acc[mt][nt], PAh[mt].x, QAh[mt].x, PAh[mt].y, QAh[mt].y,
                         BL[nt].x, BL[nt].y);
                mma_bf16(acc[mt][nt], PAh[mt].z, QAh[mt].z, PAh[mt].w, QAh[mt].w,
                         BH[nt].z, BH[nt].w);
                mma_bf16(acc[mt][nt], PAl[mt].z, QAl[mt].z, PAl[mt].w, QAl[mt].w,
                         BH[nt].z, BH[nt].w);
                mma_bf16(acc[mt][nt], PAh[mt].z, QAh[mt].z, PAh[mt].w, QAh[mt].w,
                         BL[nt].z, BL[nt].w);
            }
        __syncthreads();
    }

    // ---- epilogue: direct float2 stores + bias ----
    #pragma unroll
    for (int mt = 0; mt < 2; mt++) {
        int row = rowBase + mOff + mt * 16 + gq;
        #pragma unroll
        for (int nt = 0; nt < 4; nt++) {
            int col = colBase + nOff + nt * 8 + 2 * tq;
            float2 bs = *(const float2*)(bias + col);
            float2 v0, v1;
            v0.x = acc[mt][nt][0] + bs.x;
            v0.y = acc[mt][nt][1] + bs.y;
            v1.x = acc[mt][nt][2] + bs.x;
            v1.y = acc[mt][nt][3] + bs.y;
            *(float2*)(C + (size_t)row * ldN + col) = v0;
            *(float2*)(C + (size_t)(row + 8) * ldN + col) = v1;
        }
    }
}

// ---------------- sampling kernel: softmax + bilinear gather ----------------
// 2 queries per block, 512 threads. Writes packed bf16 hi/lo mid for GEMM2.
__global__ __launch_bounds__(512) void msda_sample_kernel(
    const float* __restrict__ off,
    const float* __restrict__ awr,
    const float* __restrict__ xyref,
    const float* __restrict__ V,
    const int*   __restrict__ batch_offsets,
    const int*   __restrict__ spatial_shapes,
    uint32_t* __restrict__ midp,
    int Q)
{
    const int tid  = threadIdx.x;
    const int sub  = tid >> 8;
    const int stid = tid & 255;
    const int q    = blockIdx.x * 2 + sub;

    __shared__ float4 s_w[2][16][8];
    __shared__ int4   s_b[2][16][8];
    __shared__ float  s_e[2][16][8];
    __shared__ float  s_inv[2][8];

    if (stid < 128) {
        s_e[sub][stid >> 3][stid & 7] = awr[(long)q * 128 + stid];
    }
    __syncthreads();

    if (stid < 8) {
        float m = -1e30f;
        #pragma unroll
        for (int lp = 0; lp < 16; lp++) m = fmaxf(m, s_e[sub][lp][stid]);
        float s = 0.0f;
        #pragma unroll
        for (int lp = 0; lp < 16; lp++) {
            float e = __expf(s_e[sub][lp][stid] - m);
            s_e[sub][lp][stid] = e;
            s += e;
        }
        s_inv[sub][stid] = 1.0f / s;
    }
    __syncthreads();

    if (stid < 128) {
        const int lp = stid >> 3;
        const int h  = stid & 7;
        const int l  = lp >> 2;

        const int   wi  = spatial_shapes[l * 2 + 1];
        const int   hi  = spatial_shapes[l * 2 + 0];
        const float wsz = (float)wi;
        const float hsz = (float)hi;
        const int   wcap = wi - 1;
        const int   hcap = hi - 1;

        float rx = fminf(fmaxf(xyref[(long)q * 2 + 0], 0.0f), 1.0f);
        float ry = fminf(fmaxf(xyref[(long)q * 2 + 1], 0.0f), 1.0f);
        float invx = __logf(fminf(fmaxf(rx, EPSV), 1.0f) / fminf(fmaxf(1.0f - rx, EPSV), 1.0f));
        float invy = __logf(fminf(fmaxf(ry, EPSV), 1.0f) / fminf(fmaxf(1.0f - ry, EPSV), 1.0f));

        float ox = off[(long)q * 256 + lp * 16 + h * 2 + 0];
        float oy = off[(long)q * 256 + lp * 16 + h * 2 + 1];

        float sx = 1.0f / (1.0f + __expf(-(invx + ox)));
        float sy = 1.0f / (1.0f + __expf(-(invy + oy)));
        float locx = sx * 2.0f - 1.0f;
        float locy = sy * 2.0f - 1.0f;
        // NB: reference pairs loc[...,0] with w_sz and uses x as the FIRST
        // spatial index (H axis). Replicate exactly.
        float x = ((locx + 1.0f) * wsz - 1.0f) * 0.5f;
        float y = ((locy + 1.0f) * hsz - 1.0f) * 0.5f;

        int x0 = (int)floorf(x);
        int y0 = (int)floorf(y);
        int x1c = min(max(x0 + 1, 0), wcap);
        int x0c = min(max(x0,     0), wcap);
        int y1c = min(max(y0 + 1, 0), hcap);
        int y0c = min(max(y0,     0), hcap);

        float x0f = (float)x0c, x1f = (float)x1c;
        float y0f = (float)y0c, y1f = (float)y1c;
        float wa = (x1f - x) * (y1f - y);
        float wb = (x1f - x) * (y - y0f);
        float wc = (x - x0f) * (y1f - y);
        float wd = (x - x0f) * (y - y0f);

        float aw = s_e[sub][lp][h] * s_inv[sub][h];

        int b  = (q >= batch_offsets[1]) ? 1 : 0;
        int bb = b * HMAXC;
        int hd = h * HEAD_DIM;
        int base00 = (((bb + x0c) * WMAXC + y0c) * N_LEVELS + l) * EMBED_DIM + hd;
        int base01 = (((bb + x0c) * WMAXC + y1c) * N_LEVELS + l) * EMBED_DIM + hd;
        int base10 = (((bb + x1c) * WMAXC + y0c) * N_LEVELS + l) * EMBED_DIM + hd;
        int base11 = (((bb + x1c) * WMAXC + y1c) * N_LEVELS + l) * EMBED_DIM + hd;

        s_w[sub][lp][h] = make_float4(wa * aw, wb * aw, wc * aw, wd * aw);
        s_b[sub][lp][h] = make_int4(base00, base01, base10, base11);
    }
    __syncthreads();

    const int h = (stid >> 5) & 7;
    const int d = stid & 31;
    float acc = 0.0f;
    #pragma unroll 4
    for (int lp = 0; lp < 16; lp++) {
        float4 w  = s_w[sub][lp][h];
        int4   bs = s_b[sub][lp][h];
        float v0 = __ldg(V + bs.x + d);
        float v1 = __ldg(V + bs.y + d);
        float v2 = __ldg(V + bs.z + d);
        float v3 = __ldg(V + bs.w + d);
        acc = fmaf(w.x, v0, acc);
        acc = fmaf(w.y, v1, acc);
        acc = fmaf(w.z, v2, acc);
        acc = fmaf(w.w, v3, acc);
    }

    // pack (c, c+1) pairs into bf16 hi/lo planes of midA (widx2 layout)
    float nbr = __shfl_xor_sync(0xffffffffu, acc, 1);
    if ((d & 1) == 0) {
        uint32_t hw, lw;
        bf16split2(acc, nbr, hw, lw);
        int c  = h * 32 + d;
        int kp = c >> 1;
        int ch = kp >> 4;
        int w  = widx2(kp & 15);
        size_t base = ((size_t)ch * Q + q) * 16 + w;
        size_t pstr = (size_t)NCH * Q * 16;
        midp[base]        = hw;
        midp[pstr + base] = lw;
    }
}

// ---------------- launch ----------------
extern "C" void kernel_launch(void* const* d_in, const int* in_sizes, int n_in,
                              void* d_out, int out_size)
{
    const float* query  = (const float*)d_in[0];
    const float* xyref  = (const float*)d_in[1];
    const float* V      = (const float*)d_in[2];
    const float* W_off  = (const float*)d_in[3];
    const float* b_off  = (const float*)d_in[4];
    const float* W_attn = (const float*)d_in[5];
    const float* b_attn = (const float*)d_in[6];
    const float* W_out  = (const float*)d_in[7];
    const float* b_out  = (const float*)d_in[8];
    const int* batch_offsets  = (const int*)d_in[9];
    const int* spatial_shapes = (const int*)d_in[10];
    float* out = (float*)d_out;

    const int Q = in_sizes[0] / EMBED_DIM;

    float *p_off, *p_aw;
    uint32_t *p_qA, *p_midA, *p_Woff, *p_Watt, *p_Wout;
    cudaGetSymbolAddress((void**)&p_off,  g_off);
    cudaGetSymbolAddress((void**)&p_aw,   g_aw);
    cudaGetSymbolAddress((void**)&p_qA,   g_qA);
    cudaGetSymbolAddress((void**)&p_midA, g_midA);
    cudaGetSymbolAddress((void**)&p_Woff, g_Woff);
    cudaGetSymbolAddress((void**)&p_Watt, g_Watt);
    cudaGetSymbolAddress((void**)&p_Wout, g_Wout);

    cudaFuncSetAttribute(gemm_packed_kernel,
                         cudaFuncAttributeMaxDynamicSharedMemorySize, GEMM_SMEM);

    // single merged prepack: query + all 3 weight matrices
    prepack_all_kernel<<<dim3(NCH, Q / 128 + 5), 128>>>(
        query, W_off, W_attn, W_out,
        p_qA, p_Woff, p_Watt, p_Wout, Q);

    // fused GEMM1: off (4 col-blocks of 64) + aw (2 col-blocks of 64)
    gemm_packed_kernel<<<dim3(6, Q / 128), 256, GEMM_SMEM>>>(
        p_qA, Q,
        p_Woff, b_off, p_off, EMBED_DIM, 4,
        p_Watt, b_attn, p_aw, 128);

    // softmax + deformable sampling -> packed mid (2 queries per block)
    msda_sample_kernel<<<Q / 2, 512>>>(
        p_off, p_aw, xyref, V, batch_offsets, spatial_shapes, p_midA, Q);

    // GEMM2: out = mid @ W_out + b_out (4 col-blocks of 64)
    gemm_packed_kernel<<<dim3(4, Q / 128), 256, GEMM_SMEM>>>(
        p_midA, Q,
        p_Wout, b_out, out, EMBED_DIM, 4,
        nullptr, nullptr, nullptr, 128);
}

// round 12
// speedup vs baseline: 1.1278x; 1.0225x over previous
#include <cuda_runtime.h>
#include <cuda_bf16.h>
#include <math.h>
#include <stdint.h>

// ---------------- problem constants ----------------
#define EMBED_DIM 256
#define N_LEVELS  4
#define N_POINTS  4
#define N_HEADS   8
#define HEAD_DIM  32
#define HMAXC     128
#define WMAXC     128
#define MAX_Q     8192
#define NCH       8          // K=256 / 32
#define EPSV      1e-5f

// ---------------- scratch (allocation-free) ----------------
__device__ float    g_off [MAX_Q * EMBED_DIM];
__device__ float    g_aw  [MAX_Q * (N_LEVELS * N_POINTS * N_HEADS)];
__device__ uint32_t g_qA  [2 * NCH * MAX_Q * 16];   // packed query (hi/lo planes)
__device__ uint32_t g_midA[2 * NCH * MAX_Q * 16];   // packed mid
__device__ uint32_t g_Woff [2 * NCH * 256 * 16];
__device__ uint32_t g_Watt [2 * NCH * 128 * 16];
__device__ uint32_t g_Wout [2 * NCH * 256 * 16];

// ---------------- bf16 helpers ----------------
__device__ __forceinline__ uint32_t pack_bf16x2(float lo, float hi) {
    uint32_t r;
    asm("cvt.rn.bf16x2.f32 %0, %1, %2;" : "=r"(r) : "f"(hi), "f"(lo));
    return r;
}
__device__ __forceinline__ float bf16lo_f(uint32_t w) { return __uint_as_float(w << 16); }
__device__ __forceinline__ float bf16hi_f(uint32_t w) { return __uint_as_float(w & 0xffff0000u); }

__device__ __forceinline__ void bf16split2(float x, float y, uint32_t& h, uint32_t& l) {
    h = pack_bf16x2(x, y);
    l = pack_bf16x2(x - bf16lo_f(h), y - bf16hi_f(h));
}

__device__ __forceinline__ void mma_bf16(float* d,
    uint32_t a0, uint32_t a1, uint32_t a2, uint32_t a3,
    uint32_t b0, uint32_t b1) {
    asm volatile(
        "mma.sync.aligned.m16n8k16.row.col.f32.bf16.bf16.f32 "
        "{%0,%1,%2,%3}, {%4,%5,%6,%7}, {%8,%9}, {%0,%1,%2,%3};\n"
        : "+f"(d[0]), "+f"(d[1]), "+f"(d[2]), "+f"(d[3])
        : "r"(a0), "r"(a1), "r"(a2), "r"(a3), "r"(b0), "r"(b1));
}

// step-innermost permutation: kpair kw (0..15) -> (kw&3)*4 + (kw>>3)*2 + ((kw>>2)&1)
__device__ __forceinline__ int widx2(int kw) {
    return (kw & 3) * 4 + (kw >> 3) * 2 + ((kw >> 2) & 1);
}

// ---------------- cp.async (L1-bypass) ----------------
#define CP_ASYNC16(dst, src) \
    asm volatile("cp.async.cg.shared.global [%0], [%1], 16;\n" :: "r"(dst), "l"(src))
#define CP_COMMIT() asm volatile("cp.async.commit_group;\n" ::: "memory")
#define CP_WAIT(n)  asm volatile("cp.async.wait_group %0;\n" :: "n"(n) : "memory")

// ================= single merged prepack kernel =================
__global__ __launch_bounds__(128) void prepack_all_kernel(
    const float* __restrict__ query,
    const float* __restrict__ W_off, const float* __restrict__ W_attn,
    const float* __restrict__ W_out,
    uint32_t* __restrict__ pq, uint32_t* __restrict__ pwoff,
    uint32_t* __restrict__ pwatt, uint32_t* __restrict__ pwout,
    int Q)
{
    const int ch  = blockIdx.x;
    const int seg = blockIdx.y;
    const int nQseg = Q >> 7;
    const int tid = threadIdx.x;

    uint32_t hw[16], lw[16];

    if (seg < nQseg) {
        const int row = seg * 128 + tid;
        const float* src = query + (size_t)row * (NCH * 32) + ch * 32;
        #pragma unroll
        for (int kw = 0; kw < 16; kw++) {
            float2 v = *(const float2*)(src + 2 * kw);
            int w = widx2(kw);
            bf16split2(v.x, v.y, hw[w], lw[w]);
        }
        size_t base = ((size_t)ch * Q + row) * 16;
        size_t pstr = (size_t)NCH * Q * 16;
        #pragma unroll
        for (int g = 0; g < 4; g++) {
            *(uint4*)&pq[base + g * 4]        = *(uint4*)&hw[g * 4];
            *(uint4*)&pq[pstr + base + g * 4] = *(uint4*)&lw[g * 4];
        }
    } else {
        const int wseg = seg - nQseg;
        const float* B; uint32_t* out; int N; int colOff;
        if (wseg == 0)      { B = W_off;  out = pwoff; N = 256; colOff = 0;   }
        else if (wseg == 1) { B = W_off;  out = pwoff; N = 256; colOff = 128; }
        else if (wseg == 2) { B = W_attn; out = pwatt; N = 128; colOff = 0;   }
        else if (wseg == 3) { B = W_out;  out = pwout; N = 256; colOff = 0;   }
        else                { B = W_out;  out = pwout; N = 256; colOff = 128; }
        const int n = colOff + tid;
        #pragma unroll
        for (int kw = 0; kw < 16; kw++) {
            int k = ch * 32 + 2 * kw;
            float x = B[(size_t)k * N + n];
            float y = B[(size_t)(k + 1) * N + n];
            int w = widx2(kw);
            bf16split2(x, y, hw[w], lw[w]);
        }
        size_t base = ((size_t)ch * N + n) * 16;
        size_t pstr = (size_t)NCH * N * 16;
        #pragma unroll
        for (int g = 0; g < 4; g++) {
            *(uint4*)&out[base + g * 4]        = *(uint4*)&hw[g * 4];
            *(uint4*)&out[pstr + base + g * 4] = *(uint4*)&lw[g * 4];
        }
    }
}

// ================ bf16x3 mma GEMM on prepacked operands ================
// CTA tile 128x64, 256 threads, 8 warps (4m x 2n), warp tile 32x32.
// Dense smem (16 words/row), 4-buffer ring, prefetch distance 2, 1 sync/chunk.
#define A_W (128 * 16)             // 2048 words per A plane
#define B_W (64 * 16)              // 1024 words per B plane
#define BUF_W (2 * A_W + 2 * B_W)  // 6144 words per buffer
#define NBUF 4
#define GEMM_SMEM (NBUF * BUF_W * 4)  // 98304 bytes

__global__ __launch_bounds__(256, 2) void gemm_packed_kernel(
    const uint32_t* __restrict__ Ap, int Qrows,
    const uint32_t* __restrict__ Bp0, const float* __restrict__ bias0,
    float* __restrict__ C0, int N0, int nb0,
    const uint32_t* __restrict__ Bp1, const float* __restrict__ bias1,
    float* __restrict__ C1, int N1)
{
    extern __shared__ uint32_t sm[];
    const int tid = threadIdx.x;
    const int lid = tid & 31;
    const int wid = tid >> 5;
    const int rowBase = blockIdx.y * 128;

    const uint32_t* Bp; const float* bias; float* C; int ldN; int colBase;
    if ((int)blockIdx.x < nb0) {
        Bp = Bp0; bias = bias0; C = C0; ldN = N0; colBase = blockIdx.x * 64;
    } else {
        Bp = Bp1; bias = bias1; C = C1; ldN = N1; colBase = (blockIdx.x - nb0) * 64;
    }

    const size_t Astr = (size_t)NCH * Qrows * 16;   // plane stride (words)
    const size_t Bstr = (size_t)NCH * ldN * 16;
    const size_t dA   = (size_t)Qrows * 16;         // per-chunk delta (words)
    const size_t dB   = (size_t)ldN * 16;

    const int mOff = (wid >> 1) * 32;
    const int nOff = (wid & 1) * 32;
    const int gq = lid >> 2;
    const int tq = lid & 3;

    // ---- hoisted per-thread staging addresses ----
    const uint32_t* aP[4]; uint32_t aD[4];
    const uint32_t* bP[2]; uint32_t bD[2];
    #pragma unroll
    for (int i = 0; i < 4; i++) {
        int s = tid + i * 256, pl = s >> 9, rem = s & 511;
        aP[i] = Ap + (size_t)pl * Astr + (size_t)rowBase * 16 + rem * 4;
        aD[i] = pl * A_W + rem * 4;
    }
    #pragma unroll
    for (int i = 0; i < 2; i++) {
        int s = tid + i * 256, pl = s >> 8, rem = s & 255;
        bP[i] = Bp + (size_t)pl * Bstr + (size_t)colBase * 16 + rem * 4;
        bD[i] = 2 * A_W + pl * B_W + rem * 4;
    }
    uint32_t sbase[NBUF];
    #pragma unroll
    for (int b = 0; b < NBUF; b++)
        sbase[b] = (uint32_t)__cvta_generic_to_shared(sm + b * BUF_W);

    float acc[2][4][4];
    #pragma unroll
    for (int mt = 0; mt < 2; mt++)
        #pragma unroll
        for (int nt = 0; nt < 4; nt++)
            #pragma unroll
            for (int j = 0; j < 4; j++)
                acc[mt][nt][j] = 0.0f;

    auto issue = [&](int ch) {
        uint32_t sb = sbase[ch & (NBUF - 1)];
        size_t oA = ch * dA, oB = ch * dB;
        #pragma unroll
        for (int i = 0; i < 4; i++)
            CP_ASYNC16(sb + (aD[i] << 2), aP[i] + oA);
        #pragma unroll
        for (int i = 0; i < 2; i++)
            CP_ASYNC16(sb + (bD[i] << 2), bP[i] + oB);
        CP_COMMIT();
    };

    issue(0);
    issue(1);

    for (int ch = 0; ch < NCH; ch++) {
        if (ch + 2 < NCH) { issue(ch + 2); CP_WAIT(2); }
        else if (ch + 1 < NCH) { CP_WAIT(1); }
        else { CP_WAIT(0); }
        __syncthreads();

        const uint32_t* bAh = sm + (ch & (NBUF - 1)) * BUF_W;
        const uint32_t* bAl = bAh + A_W;
        const uint32_t* bBh = bAh + 2 * A_W;
        const uint32_t* bBl = bBh + B_W;

        // ---- 16 LDS.128: all fragments for both k16 steps ----
        uint4 PAh[2], QAh[2], PAl[2], QAl[2];
        uint4 BH[4], BL[4];
        #pragma unroll
        for (int mt = 0; mt < 2; mt++) {
            int row = mOff + mt * 16 + gq;
            PAh[mt] = *(const uint4*)&bAh[row * 16 + tq * 4];
            QAh[mt] = *(const uint4*)&bAh[(row + 8) * 16 + tq * 4];
            PAl[mt] = *(const uint4*)&bAl[row * 16 + tq * 4];
            QAl[mt] = *(const uint4*)&bAl[(row + 8) * 16 + tq * 4];
        }
        #pragma unroll
        for (int nt = 0; nt < 4; nt++) {
            int col = nOff + nt * 8 + gq;
            BH[nt] = *(const uint4*)&bBh[col * 16 + tq * 4];
            BL[nt] = *(const uint4*)&bBl[col * 16 + tq * 4];
        }

        // ---- 48 HMMA ----
        #pragma unroll
        for (int mt = 0; mt < 2; mt++)
            #pragma unroll
            for (int nt = 0; nt < 4; nt++) {
                mma_bf16(acc[mt][nt], PAh[mt].x, QAh[mt].x, PAh[mt].y, QAh[mt].y,
                         BH[nt].x, BH[nt].y);
                mma_bf16(acc[mt][nt], PAl[mt].x, QAl[mt].x, PAl[mt].y, QAl[mt].y,
                         BH[nt].x, BH[nt].y);
                mma_bf16(acc[mt][nt], PAh[mt].x, QAh[mt].x, PAh[mt].y, QAh[mt].y,
                         BL[nt].x, BL[nt].y);
                mma_bf16(acc[mt][nt], PAh[mt].z, QAh[mt].z, PAh[mt].w, QAh[mt].w,
                         BH[nt].z, BH[nt].w);
                mma_bf16(acc[mt][nt], PAl[mt].z, QAl[mt].z, PAl[mt].w, QAl[mt].w,
                         BH[nt].z, BH[nt].w);
                mma_bf16(acc[mt][nt], PAh[mt].z, QAh[mt].z, PAh[mt].w, QAh[mt].w,
                         BL[nt].z, BL[nt].w);
            }
        // no trailing sync: NBUF=4 ring keeps writers >=2 buffers from readers
    }

    // ---- epilogue: direct float2 stores + bias ----
    #pragma unroll
    for (int mt = 0; mt < 2; mt++) {
        int row = rowBase + mOff + mt * 16 + gq;
        #pragma unroll
        for (int nt = 0; nt < 4; nt++) {
            int col = colBase + nOff + nt * 8 + 2 * tq;
            float2 bs = *(const float2*)(bias + col);
            float2 v0, v1;
            v0.x = acc[mt][nt][0] + bs.x;
            v0.y = acc[mt][nt][1] + bs.y;
            v1.x = acc[mt][nt][2] + bs.x;
            v1.y = acc[mt][nt][3] + bs.y;
            *(float2*)(C + (size_t)row * ldN + col) = v0;
            *(float2*)(C + (size_t)(row + 8) * ldN + col) = v1;
        }
    }
}

// ---------------- sampling kernel: softmax + bilinear gather ----------------
__global__ __launch_bounds__(512) void msda_sample_kernel(
    const float* __restrict__ off,
    const float* __restrict__ awr,
    const float* __restrict__ xyref,
    const float* __restrict__ V,
    const int*   __restrict__ batch_offsets,
    const int*   __restrict__ spatial_shapes,
    uint32_t* __restrict__ midp,
    int Q)
{
    const int tid  = threadIdx.x;
    const int sub  = tid >> 8;
    const int stid = tid & 255;
    const int q    = blockIdx.x * 2 + sub;

    __shared__ float4 s_w[2][16][8];
    __shared__ int4   s_b[2][16][8];
    __shared__ float  s_e[2][16][8];
    __shared__ float  s_inv[2][8];

    if (stid < 128) {
        s_e[sub][stid >> 3][stid & 7] = awr[(long)q * 128 + stid];
    }
    __syncthreads();

    if (stid < 8) {
        float m = -1e30f;
        #pragma unroll
        for (int lp = 0; lp < 16; lp++) m = fmaxf(m, s_e[sub][lp][stid]);
        float s = 0.0f;
        #pragma unroll
        for (int lp = 0; lp < 16; lp++) {
            float e = __expf(s_e[sub][lp][stid] - m);
            s_e[sub][lp][stid] = e;
            s += e;
        }
        s_inv[sub][stid] = 1.0f / s;
    }
    __syncthreads();

    if (stid < 128) {
        const int lp = stid >> 3;
        const int h  = stid & 7;
        const int l  = lp >> 2;

        const int   wi  = spatial_shapes[l * 2 + 1];
        const int   hi  = spatial_shapes[l * 2 + 0];
        const float wsz = (float)wi;
        const float hsz = (float)hi;
        const int   wcap = wi - 1;
        const int   hcap = hi - 1;

        float rx = fminf(fmaxf(xyref[(long)q * 2 + 0], 0.0f), 1.0f);
        float ry = fminf(fmaxf(xyref[(long)q * 2 + 1], 0.0f), 1.0f);
        float invx = __logf(fminf(fmaxf(rx, EPSV), 1.0f) / fminf(fmaxf(1.0f - rx, EPSV), 1.0f));
        float invy = __logf(fminf(fmaxf(ry, EPSV), 1.0f) / fminf(fmaxf(1.0f - ry, EPSV), 1.0f));

        float ox = off[(long)q * 256 + lp * 16 + h * 2 + 0];
        float oy = off[(long)q * 256 + lp * 16 + h * 2 + 1];

        float sx = 1.0f / (1.0f + __expf(-(invx + ox)));
        float sy = 1.0f / (1.0f + __expf(-(invy + oy)));
        float locx = sx * 2.0f - 1.0f;
        float locy = sy * 2.0f - 1.0f;
        // NB: reference pairs loc[...,0] with w_sz and uses x as the FIRST
        // spatial index (H axis). Replicate exactly.
        float x = ((locx + 1.0f) * wsz - 1.0f) * 0.5f;
        float y = ((locy + 1.0f) * hsz - 1.0f) * 0.5f;

        int x0 = (int)floorf(x);
        int y0 = (int)floorf(y);
        int x1c = min(max(x0 + 1, 0), wcap);
        int x0c = min(max(x0,     0), wcap);
        int y1c = min(max(y0 + 1, 0), hcap);
        int y0c = min(max(y0,     0), hcap);

        float x0f = (float)x0c, x1f = (float)x1c;
        float y0f = (float)y0c, y1f = (float)y1c;
        float wa = (x1f - x) * (y1f - y);
        float wb = (x1f - x) * (y - y0f);
        float wc = (x - x0f) * (y1f - y);
        float wd = (x - x0f) * (y - y0f);

        float aw = s_e[sub][lp][h] * s_inv[sub][h];

        int b  = (q >= batch_offsets[1]) ? 1 : 0;
        int bb = b * HMAXC;
        int hd = h * HEAD_DIM;
        int base00 = (((bb + x0c) * WMAXC + y0c) * N_LEVELS + l) * EMBED_DIM + hd;
        int base01 = (((bb + x0c) * WMAXC + y1c) * N_LEVELS + l) * EMBED_DIM + hd;
        int base10 = (((bb + x1c) * WMAXC + y0c) * N_LEVELS + l) * EMBED_DIM + hd;
        int base11 = (((bb + x1c) * WMAXC + y1c) * N_LEVELS + l) * EMBED_DIM + hd;

        s_w[sub][lp][h] = make_float4(wa * aw, wb * aw, wc * aw, wd * aw);
        s_b[sub][lp][h] = make_int4(base00, base01, base10, base11);
    }
    __syncthreads();

    const int h = (stid >> 5) & 7;
    const int d = stid & 31;
    float acc = 0.0f;
    #pragma unroll 4
    for (int lp = 0; lp < 16; lp++) {
        float4 w  = s_w[sub][lp][h];
        int4   bs = s_b[sub][lp][h];
        float v0 = __ldg(V + bs.x + d);
        float v1 = __ldg(V + bs.y + d);
        float v2 = __ldg(V + bs.z + d);
        float v3 = __ldg(V + bs.w + d);
        acc = fmaf(w.x, v0, acc);
        acc = fmaf(w.y, v1, acc);
        acc = fmaf(w.z, v2, acc);
        acc = fmaf(w.w, v3, acc);
    }

    // pack (c, c+1) pairs into bf16 hi/lo planes of midA (widx2 layout)
    float nbr = __shfl_xor_sync(0xffffffffu, acc, 1);
    if ((d & 1) == 0) {
        uint32_t hw, lw;
        bf16split2(acc, nbr, hw, lw);
        int c  = h * 32 + d;
        int kp = c >> 1;
        int ch = kp >> 4;
        int w  = widx2(kp & 15);
        size_t base = ((size_t)ch * Q + q) * 16 + w;
        size_t pstr = (size_t)NCH * Q * 16;
        midp[base]        = hw;
        midp[pstr + base] = lw;
    }
}

// ---------------- launch ----------------
extern "C" void kernel_launch(void* const* d_in, const int* in_sizes, int n_in,
                              void* d_out, int out_size)
{
    const float* query  = (const float*)d_in[0];
    const float* xyref  = (const float*)d_in[1];
    const float* V      = (const float*)d_in[2];
    const float* W_off  = (const float*)d_in[3];
    const float* b_off  = (const float*)d_in[4];
    const float* W_attn = (const float*)d_in[5];
    const float* b_attn = (const float*)d_in[6];
    const float* W_out  = (const float*)d_in[7];
    const float* b_out  = (const float*)d_in[8];
    const int* batch_offsets  = (const int*)d_in[9];
    const int* spatial_shapes = (const int*)d_in[10];
    float* out = (float*)d_out;

    const int Q = in_sizes[0] / EMBED_DIM;

    float *p_off, *p_aw;
    uint32_t *p_qA, *p_midA, *p_Woff, *p_Watt, *p_Wout;
    cudaGetSymbolAddress((void**)&p_off,  g_off);
    cudaGetSymbolAddress((void**)&p_aw,   g_aw);
    cudaGetSymbolAddress((void**)&p_qA,   g_qA);
    cudaGetSymbolAddress((void**)&p_midA, g_midA);
    cudaGetSymbolAddress((void**)&p_Woff, g_Woff);
    cudaGetSymbolAddress((void**)&p_Watt, g_Watt);
    cudaGetSymbolAddress((void**)&p_Wout, g_Wout);

    cudaFuncSetAttribute(gemm_packed_kernel,
                         cudaFuncAttributeMaxDynamicSharedMemorySize, GEMM_SMEM);

    // single merged prepack: query + all 3 weight matrices
    prepack_all_kernel<<<dim3(NCH, Q / 128 + 5), 128>>>(
        query, W_off, W_attn, W_out,
        p_qA, p_Woff, p_Watt, p_Wout, Q);

    // fused GEMM1: off (4 col-blocks of 64) + aw (2 col-blocks of 64)
    gemm_packed_kernel<<<dim3(6, Q / 128), 256, GEMM_SMEM>>>(
        p_qA, Q,
        p_Woff, b_off, p_off, EMBED_DIM, 4,
        p_Watt, b_attn, p_aw, 128);

    // softmax + deformable sampling -> packed mid (2 queries per block)
    msda_sample_kernel<<<Q / 2, 512>>>(
        p_off, p_aw, xyref, V, batch_offsets, spatial_shapes, p_midA, Q);

    // GEMM2: out = mid @ W_out + b_out (4 col-blocks of 64)
    gemm_packed_kernel<<<dim3(4, Q / 128), 256, GEMM_SMEM>>>(
        p_midA, Q,
        p_Wout, b_out, out, EMBED_DIM, 4,
        nullptr, nullptr, nullptr, 128);
}